// round 5
// baseline (speedup 1.0000x reference)
#include <cuda_runtime.h>
#include <math.h>
#include <stdint.h>

#define N_NODES  50000
#define N_EDGES  800000
#define N_GRAPHS 256
#define DMAX     512
#define GRUH     256
#define NPART    196   // ceil(50000/256)

// ---------------- scratch (device globals; no allocation allowed) ----------------
__device__ __align__(16) float g_h   [(size_t)N_NODES * DMAX];
__device__ __align__(16) float g_buf0[(size_t)N_NODES * DMAX];
__device__ __align__(16) float g_buf1[(size_t)N_NODES * DMAX];
__device__ float g_dinv[N_NODES];
__device__ int   g_counts[N_NODES];
__device__ int   g_cursor[N_NODES];
__device__ int   g_offs[N_NODES + 1];
__device__ int   g_part[NPART];
__device__ int   g_csrc[N_EDGES];
__device__ int   g_gcounts[N_GRAPHS];
__device__ int   g_goffs[N_GRAPHS + 1];
__device__ float g_gate[N_NODES];
__device__ __align__(16) float g_emb[N_GRAPHS * 512];
__device__ float g_h1[N_GRAPHS * GRUH];
__device__ float g_h2[N_GRAPHS * GRUH];
__device__ int   g_is64;

// ---------------- packed fp32x2 helpers (Blackwell FFMA2 — PTX-only) ----------------
__device__ __forceinline__ unsigned long long pk2(float lo, float hi) {
    unsigned long long r;
    asm("mov.b64 %0, {%1, %2};" : "=l"(r) : "f"(lo), "f"(hi));
    return r;
}
__device__ __forceinline__ unsigned long long f2fma(unsigned long long a,
                                                    unsigned long long b,
                                                    unsigned long long c) {
    unsigned long long d;
    asm("fma.rn.f32x2 %0, %1, %2, %3;" : "=l"(d) : "l"(a), "l"(b), "l"(c));
    return d;
}
__device__ __forceinline__ float2 upk2(unsigned long long v) {
    float2 f;
    asm("mov.b64 {%0, %1}, %2;" : "=f"(f.x), "=f"(f.y) : "l"(v));
    return f;
}

// ---------------- index-width detection (int64 vs int32 inputs) ----------------
__global__ void detect_kernel(const int* __restrict__ ei_raw) {
    if (blockIdx.x == 0 && threadIdx.x == 0) {
        int is64 = 1;
        for (int i = 0; i < 128; i++) {
            if (ei_raw[2 * i + 1] != 0) { is64 = 0; break; }
        }
        g_is64 = is64;
    }
}

__device__ __forceinline__ int load_idx(const void* p, long long i, int is64) {
    return is64 ? (int)((const long long*)p)[i] : ((const int*)p)[i];
}

// ---------------- init / degree count / CSR build ----------------
__global__ void init_kernel() {
    int i = blockIdx.x * blockDim.x + threadIdx.x;
    int stride = gridDim.x * blockDim.x;
    for (int k = i; k < N_NODES; k += stride) { g_counts[k] = 0; g_cursor[k] = 0; }
    for (int k = i; k < N_GRAPHS; k += stride) g_gcounts[k] = 0;
}

__global__ void count_kernel(const void* __restrict__ ei, const void* __restrict__ batch) {
    int is64 = g_is64;
    int i = blockIdx.x * blockDim.x + threadIdx.x;
    int stride = gridDim.x * blockDim.x;
    for (int e = i; e < N_EDGES; e += stride) {
        int d = load_idx(ei, (long long)N_EDGES + e, is64);   // dst = edge_index[1]
        atomicAdd(&g_counts[d], 1);
    }
    for (int v = i; v < N_NODES; v += stride) {
        int b = load_idx(batch, v, is64);
        atomicAdd(&g_gcounts[b], 1);
    }
}

// -------- hierarchical exclusive scan of g_counts -> g_offs (3 tiny kernels) --------
__global__ void __launch_bounds__(256) part_sum_kernel() {
    __shared__ int red[8];
    int b = blockIdx.x, t = threadIdx.x;
    int i = b * 256 + t;
    int v = (i < N_NODES) ? g_counts[i] : 0;
#pragma unroll
    for (int o = 16; o > 0; o >>= 1) v += __shfl_xor_sync(0xffffffffu, v, o);
    if ((t & 31) == 0) red[t >> 5] = v;
    __syncthreads();
    if (t == 0) {
        int s = 0;
#pragma unroll
        for (int w = 0; w < 8; w++) s += red[w];
        g_part[b] = s;
    }
}

__global__ void __launch_bounds__(256) scan_parts_kernel() {
    __shared__ int sh[256];
    int t = threadIdx.x;
    // exclusive scan of NPART block sums
    int v = (t < NPART) ? g_part[t] : 0;
    sh[t] = v;
    __syncthreads();
    for (int d = 1; d < 256; d <<= 1) {
        int x = (t >= d) ? sh[t - d] : 0;
        __syncthreads();
        sh[t] += x;
        __syncthreads();
    }
    if (t < NPART) g_part[t] = sh[t] - v;
    __syncthreads();
    // exclusive scan of graph counts
    int gc = g_gcounts[t];
    sh[t] = gc;
    __syncthreads();
    for (int d = 1; d < 256; d <<= 1) {
        int x = (t >= d) ? sh[t - d] : 0;
        __syncthreads();
        sh[t] += x;
        __syncthreads();
    }
    g_goffs[t] = sh[t] - gc;
    if (t == 255) g_goffs[256] = sh[255];
}

__global__ void __launch_bounds__(256) final_scan_kernel() {
    __shared__ int sh[256];
    int b = blockIdx.x, t = threadIdx.x;
    int i = b * 256 + t;
    int v = (i < N_NODES) ? g_counts[i] : 0;
    sh[t] = v;
    __syncthreads();
    for (int d = 1; d < 256; d <<= 1) {
        int x = (t >= d) ? sh[t - d] : 0;
        __syncthreads();
        sh[t] += x;
        __syncthreads();
    }
    int base = g_part[b];
    if (i < N_NODES) g_offs[i] = base + sh[t] - v;
    if (i == N_NODES - 1) g_offs[N_NODES] = base + sh[t];
}

__global__ void dinv_kernel() {
    int i = blockIdx.x * blockDim.x + threadIdx.x;
    if (i < N_NODES) g_dinv[i] = rsqrtf((float)(g_counts[i] + 1));  // +1 self-loop
}

__global__ void fill_kernel(const void* __restrict__ ei) {
    int is64 = g_is64;
    int i = blockIdx.x * blockDim.x + threadIdx.x;
    int stride = gridDim.x * blockDim.x;
    for (int e = i; e < N_EDGES; e += stride) {
        int d = load_idx(ei, (long long)N_EDGES + e, is64);
        int s = load_idx(ei, e, is64);
        int pos = g_offs[d] + atomicAdd(&g_cursor[d], 1);
        g_csrc[pos] = s;
    }
}

// ------------- GCN aggregation BEFORE transform (Agg(X)·W == Agg(X·W)) -------------
// warp-per-node; D = input width (64/128/256) — half the traffic of post-GEMM agg.
__global__ void __launch_bounds__(256) agg64w_kernel(const float* __restrict__ h,
                                                     float* __restrict__ out)
{
    int node = blockIdx.x * 8 + (threadIdx.x >> 5);
    if (node >= N_NODES) return;
    int lane = threadIdx.x & 31;
    float wd = g_dinv[node];
    float2 acc = *(const float2*)(h + (size_t)node * 64 + lane * 2);
    float ws = wd * wd;
    acc.x *= ws; acc.y *= ws;
    int e0 = g_offs[node], e1 = g_offs[node + 1];
    for (int e = e0; e < e1; e++) {
        int s = g_csrc[e];
        float w = g_dinv[s] * wd;
        float2 v = *(const float2*)(h + (size_t)s * 64 + lane * 2);
        acc.x += v.x * w; acc.y += v.y * w;
    }
    *(float2*)(out + (size_t)node * 64 + lane * 2) = acc;
}

__global__ void __launch_bounds__(256) agg128w_kernel(const float* __restrict__ h,
                                                      float* __restrict__ out)
{
    int node = blockIdx.x * 8 + (threadIdx.x >> 5);
    if (node >= N_NODES) return;
    int lane = threadIdx.x & 31;
    float wd = g_dinv[node];
    float4 acc = *(const float4*)(h + (size_t)node * 128 + lane * 4);
    float ws = wd * wd;
    acc.x *= ws; acc.y *= ws; acc.z *= ws; acc.w *= ws;
    int e0 = g_offs[node], e1 = g_offs[node + 1];
    for (int e = e0; e < e1; e++) {
        int s = g_csrc[e];
        float w = g_dinv[s] * wd;
        float4 v = *(const float4*)(h + (size_t)s * 128 + lane * 4);
        acc.x += v.x * w; acc.y += v.y * w; acc.z += v.z * w; acc.w += v.w * w;
    }
    *(float4*)(out + (size_t)node * 128 + lane * 4) = acc;
}

__global__ void __launch_bounds__(256) agg256w_kernel(const float* __restrict__ h,
                                                      float* __restrict__ out)
{
    int node = blockIdx.x * 8 + (threadIdx.x >> 5);
    if (node >= N_NODES) return;
    int lane = threadIdx.x & 31;
    float wd = g_dinv[node];
    const float* rown = h + (size_t)node * 256;
    float4 a0 = *(const float4*)(rown + lane * 4);
    float4 a1 = *(const float4*)(rown + 128 + lane * 4);
    float ws = wd * wd;
    a0.x *= ws; a0.y *= ws; a0.z *= ws; a0.w *= ws;
    a1.x *= ws; a1.y *= ws; a1.z *= ws; a1.w *= ws;
    int e0 = g_offs[node], e1 = g_offs[node + 1];
    for (int e = e0; e < e1; e++) {
        int s = g_csrc[e];
        float w = g_dinv[s] * wd;
        const float* rs = h + (size_t)s * 256;
        float4 v0 = *(const float4*)(rs + lane * 4);
        float4 v1 = *(const float4*)(rs + 128 + lane * 4);
        a0.x += v0.x * w; a0.y += v0.y * w; a0.z += v0.z * w; a0.w += v0.w * w;
        a1.x += v1.x * w; a1.y += v1.y * w; a1.z += v1.z * w; a1.w += v1.w * w;
    }
    float* ro = out + (size_t)node * 256;
    *(float4*)(ro + lane * 4) = a0;
    *(float4*)(ro + 128 + lane * 4) = a1;
}

// ---------- SGEMM + bias + ReLU: C = relu(A[M,K] @ B[K,N] + bias), f32x2 FMA ----------
#define BM 128
#define BN 128
#define BKK 16

__global__ void __launch_bounds__(256) sgemm_br_kernel(
    const float* __restrict__ A, const float* __restrict__ B,
    const float* __restrict__ bias, float* __restrict__ C,
    int M, int N, int K)
{
    __shared__ __align__(16) float As[BKK][BM];
    __shared__ __align__(16) float Bs[BKK][BN];
    int tid = threadIdx.x;
    int row0 = blockIdx.x * BM;
    int col0 = blockIdx.y * BN;
    int tx = tid & 15, ty = tid >> 4;

    // accumulators packed over row pairs: acc2[p][j] holds rows (2p, 2p+1), col j
    unsigned long long acc2[4][8];
#pragma unroll
    for (int p = 0; p < 4; p++)
#pragma unroll
        for (int j = 0; j < 8; j++) acc2[p][j] = 0ull;

    for (int k0 = 0; k0 < K; k0 += BKK) {
#pragma unroll
        for (int l = 0; l < 2; l++) {
            int f = tid + l * 256;
            int r = f >> 2;
            int c4 = f & 3;
            int grow = row0 + r;
            float4 v = make_float4(0.f, 0.f, 0.f, 0.f);
            if (grow < M) v = *(const float4*)(A + (size_t)grow * K + k0 + c4 * 4);
            As[c4 * 4 + 0][r] = v.x;
            As[c4 * 4 + 1][r] = v.y;
            As[c4 * 4 + 2][r] = v.z;
            As[c4 * 4 + 3][r] = v.w;
        }
#pragma unroll
        for (int l = 0; l < 2; l++) {
            int f = tid + l * 256;
            int kk = f >> 5;
            int c4 = f & 31;
            float4 v = *(const float4*)(B + (size_t)(k0 + kk) * N + col0 + c4 * 4);
            *(float4*)&Bs[kk][c4 * 4] = v;
        }
        __syncthreads();
#pragma unroll
        for (int kk = 0; kk < BKK; kk++) {
            float4 va0 = *(const float4*)&As[kk][ty * 8];
            float4 va1 = *(const float4*)&As[kk][ty * 8 + 4];
            float4 vb0 = *(const float4*)&Bs[kk][tx * 8];
            float4 vb1 = *(const float4*)&Bs[kk][tx * 8 + 4];
            unsigned long long aa[4];
            aa[0] = pk2(va0.x, va0.y); aa[1] = pk2(va0.z, va0.w);
            aa[2] = pk2(va1.x, va1.y); aa[3] = pk2(va1.z, va1.w);
            unsigned long long bb[8];
            bb[0] = pk2(vb0.x, vb0.x); bb[1] = pk2(vb0.y, vb0.y);
            bb[2] = pk2(vb0.z, vb0.z); bb[3] = pk2(vb0.w, vb0.w);
            bb[4] = pk2(vb1.x, vb1.x); bb[5] = pk2(vb1.y, vb1.y);
            bb[6] = pk2(vb1.z, vb1.z); bb[7] = pk2(vb1.w, vb1.w);
#pragma unroll
            for (int p = 0; p < 4; p++)
#pragma unroll
                for (int j = 0; j < 8; j++)
                    acc2[p][j] = f2fma(aa[p], bb[j], acc2[p][j]);
        }
        __syncthreads();
    }

    float4 bb0 = *(const float4*)(bias + col0 + tx * 8);
    float4 bb1 = *(const float4*)(bias + col0 + tx * 8 + 4);
    float bv[8] = {bb0.x, bb0.y, bb0.z, bb0.w, bb1.x, bb1.y, bb1.z, bb1.w};
#pragma unroll
    for (int p = 0; p < 4; p++) {
        float2 f[8];
#pragma unroll
        for (int j = 0; j < 8; j++) f[j] = upk2(acc2[p][j]);
#pragma unroll
        for (int half = 0; half < 2; half++) {
            int grow = row0 + ty * 8 + 2 * p + half;
            if (grow < M) {
                float vals[8];
#pragma unroll
                for (int j = 0; j < 8; j++) {
                    float v = half ? f[j].y : f[j].x;
                    vals[j] = fmaxf(v + bv[j], 0.f);
                }
                float* crow = C + (size_t)grow * N + col0 + tx * 8;
                *(float4*)(crow)     = make_float4(vals[0], vals[1], vals[2], vals[3]);
                *(float4*)(crow + 4) = make_float4(vals[4], vals[5], vals[6], vals[7]);
            }
        }
    }
}

// ---------------- gate scores: gate[i] = dot(x[i,0:512], gate_w) + gate_b ----------------
__global__ void __launch_bounds__(256) gate_kernel(const float* __restrict__ gw,
                                                   const float* __restrict__ gb)
{
    int warp = (blockIdx.x * blockDim.x + threadIdx.x) >> 5;
    int lane = threadIdx.x & 31;
    if (warp >= N_NODES) return;
    const float* xr = g_buf0 + (size_t)warp * 512;
    float s = 0.f;
#pragma unroll 4
    for (int k = lane; k < 512; k += 32) s += xr[k] * gw[k];
#pragma unroll
    for (int o = 16; o > 0; o >>= 1) s += __shfl_xor_sync(0xffffffffu, s, o);
    if (lane == 0) g_gate[warp] = s + gb[0];
}

// ---------------- segment softmax + weighted sum -> graph embeddings [G, 512] ----------------
__global__ void __launch_bounds__(256) softmax_emb_kernel()
{
    __shared__ float red[8];
    __shared__ float salpha[256];
    __shared__ float bcast;
    int g = blockIdx.x, tid = threadIdx.x;
    int lane = tid & 31, wid = tid >> 5;
    int s = g_goffs[g], e = g_goffs[g + 1];

    float m = -INFINITY;
    for (int i = s + tid; i < e; i += 256) m = fmaxf(m, g_gate[i]);
#pragma unroll
    for (int o = 16; o > 0; o >>= 1) m = fmaxf(m, __shfl_xor_sync(0xffffffffu, m, o));
    if (lane == 0) red[wid] = m;
    __syncthreads();
    if (wid == 0) {
        float t = (lane < 8) ? red[lane] : -INFINITY;
#pragma unroll
        for (int o = 4; o > 0; o >>= 1) t = fmaxf(t, __shfl_xor_sync(0xffffffffu, t, o));
        if (lane == 0) bcast = t;
    }
    __syncthreads();
    m = bcast;

    float sum = 0.f;
    for (int i = s + tid; i < e; i += 256) sum += expf(g_gate[i] - m);
#pragma unroll
    for (int o = 16; o > 0; o >>= 1) sum += __shfl_xor_sync(0xffffffffu, sum, o);
    if (lane == 0) red[wid] = sum;
    __syncthreads();
    if (wid == 0) {
        float t = (lane < 8) ? red[lane] : 0.f;
#pragma unroll
        for (int o = 4; o > 0; o >>= 1) t += __shfl_xor_sync(0xffffffffu, t, o);
        if (lane == 0) bcast = t;
    }
    __syncthreads();
    float inv = (e > s) ? 1.f / bcast : 0.f;

    float acc0 = 0.f, acc1 = 0.f;
    for (int start = s; start < e; start += 256) {
        int i = start + tid;
        salpha[tid] = (i < e) ? expf(g_gate[i] - m) * inv : 0.f;
        __syncthreads();
        int cnt = min(256, e - start);
        for (int k = 0; k < cnt; k++) {
            float a = salpha[k];
            const float* xr = g_buf0 + (size_t)(start + k) * 512;
            acc0 += xr[tid] * a;
            acc1 += xr[tid + 256] * a;
        }
        __syncthreads();
    }
    g_emb[g * 512 + tid] = acc0;
    g_emb[g * 512 + 256 + tid] = acc1;
}

// ---------------- GRU cell with h=0: out = (1-z)*n ; gh = bhh (whh unused) ----------------
__global__ void __launch_bounds__(256) gru_cell_kernel(
    const float* __restrict__ xin, const float* __restrict__ wih,
    const float* __restrict__ bih, const float* __restrict__ bhh,
    float* __restrict__ hout, int K)
{
    int warp = (blockIdx.x * blockDim.x + threadIdx.x) >> 5;
    int lane = threadIdx.x & 31;
    if (warp >= N_GRAPHS * GRUH) return;
    int g = warp >> 8;
    int j = warp & 255;
    const float* xg = xin + (size_t)g * K;
    const float* wr = wih + (size_t)j * K;
    const float* wz = wih + (size_t)(j + 256) * K;
    const float* wn = wih + (size_t)(j + 512) * K;
    float sr = 0.f, sz = 0.f, sn = 0.f;
    for (int k = lane; k < K; k += 32) {
        float xv = xg[k];
        sr += xv * wr[k];
        sz += xv * wz[k];
        sn += xv * wn[k];
    }
#pragma unroll
    for (int o = 16; o > 0; o >>= 1) {
        sr += __shfl_xor_sync(0xffffffffu, sr, o);
        sz += __shfl_xor_sync(0xffffffffu, sz, o);
        sn += __shfl_xor_sync(0xffffffffu, sn, o);
    }
    if (lane == 0) {
        float r = 1.f / (1.f + expf(-(sr + bih[j] + bhh[j])));
        float z = 1.f / (1.f + expf(-(sz + bih[j + 256] + bhh[j + 256])));
        float n = tanhf(sn + bih[j + 512] + r * bhh[j + 512]);
        hout[g * GRUH + j] = (1.f - z) * n;
    }
}

// ---------------- output projection ----------------
__global__ void __launch_bounds__(256) proj_kernel(
    const float* __restrict__ h2, const float* __restrict__ pw,
    const float* __restrict__ pb, float* __restrict__ out)
{
    int warp = (blockIdx.x * blockDim.x + threadIdx.x) >> 5;
    int lane = threadIdx.x & 31;
    if (warp >= N_GRAPHS * 512) return;
    int g = warp >> 9;
    int o = warp & 511;
    const float* hr = h2 + (size_t)g * 256;
    const float* wr = pw + (size_t)o * 256;
    float s = 0.f;
#pragma unroll 4
    for (int k = lane; k < 256; k += 32) s += hr[k] * wr[k];
#pragma unroll
    for (int d = 16; d > 0; d >>= 1) s += __shfl_xor_sync(0xffffffffu, s, d);
    if (lane == 0) out[g * 512 + o] = s + pb[o];
}

// ---------------- launch ----------------
extern "C" void kernel_launch(void* const* d_in, const int* in_sizes, int n_in,
                              void* d_out, int out_size)
{
    const float* x       = (const float*)d_in[0];
    const void*  ei      = d_in[1];
    const void*  batch   = d_in[2];
    const float* w0 = (const float*)d_in[3];  const float* b0 = (const float*)d_in[4];
    const float* w1 = (const float*)d_in[5];  const float* b1 = (const float*)d_in[6];
    const float* w2 = (const float*)d_in[7];  const float* b2 = (const float*)d_in[8];
    const float* gate_w = (const float*)d_in[9];
    const float* gate_b = (const float*)d_in[10];
    const float* wih0 = (const float*)d_in[11];
    const float* bih0 = (const float*)d_in[13];
    const float* bhh0 = (const float*)d_in[14];
    const float* wih1 = (const float*)d_in[15];
    const float* bih1 = (const float*)d_in[17];
    const float* bhh1 = (const float*)d_in[18];
    const float* proj_w = (const float*)d_in[19];
    const float* proj_b = (const float*)d_in[20];
    float* out = (float*)d_out;

    float *pH, *pB0, *pB1, *pEmb, *pH1, *pH2;
    cudaGetSymbolAddress((void**)&pH,   g_h);
    cudaGetSymbolAddress((void**)&pB0,  g_buf0);
    cudaGetSymbolAddress((void**)&pB1,  g_buf1);
    cudaGetSymbolAddress((void**)&pEmb, g_emb);
    cudaGetSymbolAddress((void**)&pH1,  g_h1);
    cudaGetSymbolAddress((void**)&pH2,  g_h2);

    // preprocessing: index width, degrees, CSR offsets (hierarchical scan), norms
    detect_kernel<<<1, 32>>>((const int*)ei);
    init_kernel<<<256, 256>>>();
    count_kernel<<<1024, 256>>>(ei, batch);
    part_sum_kernel<<<NPART, 256>>>();
    scan_parts_kernel<<<1, 256>>>();
    final_scan_kernel<<<NPART, 256>>>();
    dinv_kernel<<<(N_NODES + 255) / 256, 256>>>();
    fill_kernel<<<1024, 256>>>(ei);

    int gM = (N_NODES + BM - 1) / BM;
    int gAgg = (N_NODES + 7) / 8;

    // layer 0: Agg(x)[64] -> GEMM 64->128 + b0 + relu
    agg64w_kernel<<<gAgg, 256>>>(x, pB1);
    sgemm_br_kernel<<<dim3(gM, 1), 256>>>(pB1, w0, b0, pH, N_NODES, 128, 64);
    // layer 1: Agg[128] -> GEMM 128->256 + b1 + relu
    agg128w_kernel<<<gAgg, 256>>>(pH, pB1);
    sgemm_br_kernel<<<dim3(gM, 2), 256>>>(pB1, w1, b1, pH, N_NODES, 256, 128);
    // layer 2: Agg[256] -> GEMM 256->512 + b2 + relu
    agg256w_kernel<<<gAgg, 256>>>(pH, pB1);
    sgemm_br_kernel<<<dim3(gM, 4), 256>>>(pB1, w2, b2, pB0, N_NODES, 512, 256);

    // attentional aggregation
    gate_kernel<<<(N_NODES * 32 + 255) / 256, 256>>>(gate_w, gate_b);
    softmax_emb_kernel<<<N_GRAPHS, 256>>>();

    // GRU (seq_len=1, h0=0 for both cells) + projection
    gru_cell_kernel<<<(N_GRAPHS * GRUH * 32) / 256, 256>>>(pEmb, wih0, bih0, bhh0, pH1, 512);
    gru_cell_kernel<<<(N_GRAPHS * GRUH * 32) / 256, 256>>>(pH1, wih1, bih1, bhh1, pH2, 256);
    proj_kernel<<<(N_GRAPHS * 512 * 32) / 256, 256>>>(pH2, proj_w, proj_b, out);
}

// round 6
// speedup vs baseline: 1.6001x; 1.6001x over previous
#include <cuda_runtime.h>
#include <math.h>
#include <stdint.h>

#define N_NODES  50000
#define N_EDGES  800000
#define N_GRAPHS 256
#define DMAX     512
#define GRUH     256
#define NPART    196   // ceil(50000/256)

// ---------------- scratch (device globals; no allocation allowed) ----------------
__device__ __align__(16) float g_h   [(size_t)N_NODES * DMAX];
__device__ __align__(16) float g_buf0[(size_t)N_NODES * DMAX];
__device__ __align__(16) float g_buf1[(size_t)N_NODES * DMAX];
__device__ float g_dinv[N_NODES];
__device__ int   g_counts[N_NODES];
__device__ int   g_cursor[N_NODES];
__device__ int   g_offs[N_NODES + 1];
__device__ int   g_part[NPART];
__device__ int   g_csrc[N_EDGES];
__device__ int   g_gcounts[N_GRAPHS];
__device__ int   g_goffs[N_GRAPHS + 1];
__device__ float g_gate[N_NODES];
__device__ __align__(16) float g_emb[N_GRAPHS * 512];
__device__ float g_h1[N_GRAPHS * GRUH];
__device__ float g_h2[N_GRAPHS * GRUH];
__device__ int   g_is64;

// ---------------- index-width detection (int64 vs int32 inputs) ----------------
__global__ void detect_kernel(const int* __restrict__ ei_raw) {
    if (blockIdx.x == 0 && threadIdx.x == 0) {
        int is64 = 1;
        for (int i = 0; i < 128; i++) {
            if (ei_raw[2 * i + 1] != 0) { is64 = 0; break; }
        }
        g_is64 = is64;
    }
}

__device__ __forceinline__ int load_idx(const void* p, long long i, int is64) {
    return is64 ? (int)((const long long*)p)[i] : ((const int*)p)[i];
}

// ---------------- init / degree count / CSR build ----------------
__global__ void init_kernel() {
    int i = blockIdx.x * blockDim.x + threadIdx.x;
    int stride = gridDim.x * blockDim.x;
    for (int k = i; k < N_NODES; k += stride) { g_counts[k] = 0; g_cursor[k] = 0; }
    for (int k = i; k < N_GRAPHS; k += stride) g_gcounts[k] = 0;
}

__global__ void count_kernel(const void* __restrict__ ei, const void* __restrict__ batch) {
    int is64 = g_is64;
    int i = blockIdx.x * blockDim.x + threadIdx.x;
    int stride = gridDim.x * blockDim.x;
    for (int e = i; e < N_EDGES; e += stride) {
        int d = load_idx(ei, (long long)N_EDGES + e, is64);   // dst = edge_index[1]
        atomicAdd(&g_counts[d], 1);
    }
    for (int v = i; v < N_NODES; v += stride) {
        int b = load_idx(batch, v, is64);
        atomicAdd(&g_gcounts[b], 1);
    }
}

// -------- hierarchical exclusive scan of g_counts -> g_offs --------
__global__ void __launch_bounds__(256) part_sum_kernel() {
    __shared__ int red[8];
    int b = blockIdx.x, t = threadIdx.x;
    int i = b * 256 + t;
    int v = (i < N_NODES) ? g_counts[i] : 0;
#pragma unroll
    for (int o = 16; o > 0; o >>= 1) v += __shfl_xor_sync(0xffffffffu, v, o);
    if ((t & 31) == 0) red[t >> 5] = v;
    __syncthreads();
    if (t == 0) {
        int s = 0;
#pragma unroll
        for (int w = 0; w < 8; w++) s += red[w];
        g_part[b] = s;
    }
}

__global__ void __launch_bounds__(256) scan_parts_kernel() {
    __shared__ int sh[256];
    int t = threadIdx.x;
    int v = (t < NPART) ? g_part[t] : 0;
    sh[t] = v;
    __syncthreads();
    for (int d = 1; d < 256; d <<= 1) {
        int x = (t >= d) ? sh[t - d] : 0;
        __syncthreads();
        sh[t] += x;
        __syncthreads();
    }
    if (t < NPART) g_part[t] = sh[t] - v;
    __syncthreads();
    int gc = g_gcounts[t];
    sh[t] = gc;
    __syncthreads();
    for (int d = 1; d < 256; d <<= 1) {
        int x = (t >= d) ? sh[t - d] : 0;
        __syncthreads();
        sh[t] += x;
        __syncthreads();
    }
    g_goffs[t] = sh[t] - gc;
    if (t == 255) g_goffs[256] = sh[255];
}

__global__ void __launch_bounds__(256) final_scan_kernel() {
    __shared__ int sh[256];
    int b = blockIdx.x, t = threadIdx.x;
    int i = b * 256 + t;
    int v = (i < N_NODES) ? g_counts[i] : 0;
    sh[t] = v;
    __syncthreads();
    for (int d = 1; d < 256; d <<= 1) {
        int x = (t >= d) ? sh[t - d] : 0;
        __syncthreads();
        sh[t] += x;
        __syncthreads();
    }
    int base = g_part[b];
    if (i < N_NODES) g_offs[i] = base + sh[t] - v;
    if (i == N_NODES - 1) g_offs[N_NODES] = base + sh[t];
}

__global__ void dinv_kernel() {
    int i = blockIdx.x * blockDim.x + threadIdx.x;
    if (i < N_NODES) g_dinv[i] = rsqrtf((float)(g_counts[i] + 1));  // +1 self-loop
}

__global__ void fill_kernel(const void* __restrict__ ei) {
    int is64 = g_is64;
    int i = blockIdx.x * blockDim.x + threadIdx.x;
    int stride = gridDim.x * blockDim.x;
    for (int e = i; e < N_EDGES; e += stride) {
        int d = load_idx(ei, (long long)N_EDGES + e, is64);
        int s = load_idx(ei, e, is64);
        int pos = g_offs[d] + atomicAdd(&g_cursor[d], 1);
        g_csrc[pos] = s;
    }
}

// ------------- GCN aggregation BEFORE transform (Agg(X)·W == Agg(X·W)) -------------
__global__ void __launch_bounds__(256) agg64w_kernel(const float* __restrict__ h,
                                                     float* __restrict__ out)
{
    int node = blockIdx.x * 8 + (threadIdx.x >> 5);
    if (node >= N_NODES) return;
    int lane = threadIdx.x & 31;
    float wd = g_dinv[node];
    float2 acc = *(const float2*)(h + (size_t)node * 64 + lane * 2);
    float ws = wd * wd;
    acc.x *= ws; acc.y *= ws;
    int e0 = g_offs[node], e1 = g_offs[node + 1];
    for (int e = e0; e < e1; e++) {
        int s = g_csrc[e];
        float w = g_dinv[s] * wd;
        float2 v = *(const float2*)(h + (size_t)s * 64 + lane * 2);
        acc.x += v.x * w; acc.y += v.y * w;
    }
    *(float2*)(out + (size_t)node * 64 + lane * 2) = acc;
}

__global__ void __launch_bounds__(256) agg128w_kernel(const float* __restrict__ h,
                                                      float* __restrict__ out)
{
    int node = blockIdx.x * 8 + (threadIdx.x >> 5);
    if (node >= N_NODES) return;
    int lane = threadIdx.x & 31;
    float wd = g_dinv[node];
    float4 acc = *(const float4*)(h + (size_t)node * 128 + lane * 4);
    float ws = wd * wd;
    acc.x *= ws; acc.y *= ws; acc.z *= ws; acc.w *= ws;
    int e0 = g_offs[node], e1 = g_offs[node + 1];
    for (int e = e0; e < e1; e++) {
        int s = g_csrc[e];
        float w = g_dinv[s] * wd;
        float4 v = *(const float4*)(h + (size_t)s * 128 + lane * 4);
        acc.x += v.x * w; acc.y += v.y * w; acc.z += v.z * w; acc.w += v.w * w;
    }
    *(float4*)(out + (size_t)node * 128 + lane * 4) = acc;
}

__global__ void __launch_bounds__(256) agg256w_kernel(const float* __restrict__ h,
                                                      float* __restrict__ out)
{
    int node = blockIdx.x * 8 + (threadIdx.x >> 5);
    if (node >= N_NODES) return;
    int lane = threadIdx.x & 31;
    float wd = g_dinv[node];
    const float* rown = h + (size_t)node * 256;
    float4 a0 = *(const float4*)(rown + lane * 4);
    float4 a1 = *(const float4*)(rown + 128 + lane * 4);
    float ws = wd * wd;
    a0.x *= ws; a0.y *= ws; a0.z *= ws; a0.w *= ws;
    a1.x *= ws; a1.y *= ws; a1.z *= ws; a1.w *= ws;
    int e0 = g_offs[node], e1 = g_offs[node + 1];
    for (int e = e0; e < e1; e++) {
        int s = g_csrc[e];
        float w = g_dinv[s] * wd;
        const float* rs = h + (size_t)s * 256;
        float4 v0 = *(const float4*)(rs + lane * 4);
        float4 v1 = *(const float4*)(rs + 128 + lane * 4);
        a0.x += v0.x * w; a0.y += v0.y * w; a0.z += v0.z * w; a0.w += v0.w * w;
        a1.x += v1.x * w; a1.y += v1.y * w; a1.z += v1.z * w; a1.w += v1.w * w;
    }
    float* ro = out + (size_t)node * 256;
    *(float4*)(ro + lane * 4) = a0;
    *(float4*)(ro + 128 + lane * 4) = a1;
}

// ---------------- tf32 split helpers (3xTF32 scheme, fp32-equivalent accuracy) ----------------
__device__ __forceinline__ void split_tf32(float x, uint32_t& hi, uint32_t& lo) {
    asm("cvt.rna.tf32.f32 %0, %1;" : "=r"(hi) : "f"(x));
    float r = x - __uint_as_float(hi);
    asm("cvt.rna.tf32.f32 %0, %1;" : "=r"(lo) : "f"(r));
}

__device__ __forceinline__ void mma_tf32(float* c, const uint32_t* a, const uint32_t* b) {
    asm volatile(
        "mma.sync.aligned.m16n8k8.row.col.f32.tf32.tf32.f32 "
        "{%0,%1,%2,%3}, {%4,%5,%6,%7}, {%8,%9}, {%0,%1,%2,%3};"
        : "+f"(c[0]), "+f"(c[1]), "+f"(c[2]), "+f"(c[3])
        : "r"(a[0]), "r"(a[1]), "r"(a[2]), "r"(a[3]), "r"(b[0]), "r"(b[1]));
}

// ---- GEMM + bias + ReLU via tensor cores: C = relu(A[M,K] @ B[K,N] + bias) ----
// CTA tile 128x128, BK=32; 8 warps in 2(M) x 4(N); warp = 64x32 = 4x4 m16n8k8 tiles.
#define ASTR 36
#define BSTR 132

__global__ void __launch_bounds__(256) gemm_tc_kernel(
    const float* __restrict__ A, const float* __restrict__ B,
    const float* __restrict__ bias, float* __restrict__ C,
    int M, int N, int K)
{
    __shared__ __align__(16) float As[128 * ASTR];
    __shared__ __align__(16) float Bs[32 * BSTR];

    int tid = threadIdx.x;
    int lane = tid & 31;
    int wid = tid >> 5;
    int warp_m = wid >> 2;         // 0..1
    int warp_n = wid & 3;          // 0..3
    int g = lane >> 2;             // group 0..7
    int t = lane & 3;              // thread-in-group 0..3
    int row0 = blockIdx.x * 128;
    int col0 = blockIdx.y * 128;

    float acc[4][4][4];
#pragma unroll
    for (int i = 0; i < 4; i++)
#pragma unroll
        for (int j = 0; j < 4; j++)
#pragma unroll
            for (int r = 0; r < 4; r++) acc[i][j][r] = 0.f;

    for (int k0 = 0; k0 < K; k0 += 32) {
        // load A tile [128 x 32] (guarded on M), coalesced float4
#pragma unroll
        for (int l = 0; l < 4; l++) {
            int f = tid + l * 256;
            int r = f >> 3;
            int c4 = f & 7;
            int grow = row0 + r;
            float4 v = make_float4(0.f, 0.f, 0.f, 0.f);
            if (grow < M) v = *(const float4*)(A + (size_t)grow * K + k0 + c4 * 4);
            *(float4*)&As[r * ASTR + c4 * 4] = v;
        }
        // load B tile [32 x 128]
#pragma unroll
        for (int l = 0; l < 4; l++) {
            int f = tid + l * 256;
            int kk = f >> 5;
            int c4 = f & 31;
            float4 v = *(const float4*)(B + (size_t)(k0 + kk) * N + col0 + c4 * 4);
            *(float4*)&Bs[kk * BSTR + c4 * 4] = v;
        }
        __syncthreads();

#pragma unroll
        for (int k8 = 0; k8 < 4; k8++) {
            // B fragments for this k8 across 4 n-tiles
            uint32_t bh[4][2], bl[4][2];
#pragma unroll
            for (int tn = 0; tn < 4; tn++) {
                int n = warp_n * 32 + tn * 8 + g;
                float b0 = Bs[(k8 * 8 + t) * BSTR + n];
                float b1 = Bs[(k8 * 8 + t + 4) * BSTR + n];
                split_tf32(b0, bh[tn][0], bl[tn][0]);
                split_tf32(b1, bh[tn][1], bl[tn][1]);
            }
#pragma unroll
            for (int tm = 0; tm < 4; tm++) {
                int mr = (warp_m * 64 + tm * 16 + g) * ASTR + k8 * 8 + t;
                float a0 = As[mr];
                float a1 = As[mr + 8 * ASTR];
                float a2 = As[mr + 4];
                float a3 = As[mr + 8 * ASTR + 4];
                uint32_t ah[4], al[4];
                split_tf32(a0, ah[0], al[0]);
                split_tf32(a1, ah[1], al[1]);
                split_tf32(a2, ah[2], al[2]);
                split_tf32(a3, ah[3], al[3]);
#pragma unroll
                for (int tn = 0; tn < 4; tn++) {
                    mma_tf32(acc[tm][tn], al, bh[tn]);
                    mma_tf32(acc[tm][tn], ah, bl[tn]);
                    mma_tf32(acc[tm][tn], ah, bh[tn]);
                }
            }
        }
        __syncthreads();
    }

    // epilogue: bias + relu, guarded store
#pragma unroll
    for (int tn = 0; tn < 4; tn++) {
        int col = col0 + warp_n * 32 + tn * 8 + 2 * t;
        float bv0 = bias[col];
        float bv1 = bias[col + 1];
#pragma unroll
        for (int tm = 0; tm < 4; tm++) {
            int row = row0 + warp_m * 64 + tm * 16 + g;
            if (row < M) {
                float2 v;
                v.x = fmaxf(acc[tm][tn][0] + bv0, 0.f);
                v.y = fmaxf(acc[tm][tn][1] + bv1, 0.f);
                *(float2*)(C + (size_t)row * N + col) = v;
            }
            if (row + 8 < M) {
                float2 v;
                v.x = fmaxf(acc[tm][tn][2] + bv0, 0.f);
                v.y = fmaxf(acc[tm][tn][3] + bv1, 0.f);
                *(float2*)(C + (size_t)(row + 8) * N + col) = v;
            }
        }
    }
}

// ---------------- gate scores: gate[i] = dot(x[i,0:512], gate_w) + gate_b ----------------
__global__ void __launch_bounds__(256) gate_kernel(const float* __restrict__ gw,
                                                   const float* __restrict__ gb)
{
    int warp = (blockIdx.x * blockDim.x + threadIdx.x) >> 5;
    int lane = threadIdx.x & 31;
    if (warp >= N_NODES) return;
    const float* xr = g_buf0 + (size_t)warp * 512;
    float s = 0.f;
#pragma unroll 4
    for (int k = lane; k < 512; k += 32) s += xr[k] * gw[k];
#pragma unroll
    for (int o = 16; o > 0; o >>= 1) s += __shfl_xor_sync(0xffffffffu, s, o);
    if (lane == 0) g_gate[warp] = s + gb[0];
}

// ---------------- segment softmax + weighted sum -> graph embeddings [G, 512] ----------------
__global__ void __launch_bounds__(256) softmax_emb_kernel()
{
    __shared__ float red[8];
    __shared__ float salpha[256];
    __shared__ float bcast;
    int g = blockIdx.x, tid = threadIdx.x;
    int lane = tid & 31, wid = tid >> 5;
    int s = g_goffs[g], e = g_goffs[g + 1];

    float m = -INFINITY;
    for (int i = s + tid; i < e; i += 256) m = fmaxf(m, g_gate[i]);
#pragma unroll
    for (int o = 16; o > 0; o >>= 1) m = fmaxf(m, __shfl_xor_sync(0xffffffffu, m, o));
    if (lane == 0) red[wid] = m;
    __syncthreads();
    if (wid == 0) {
        float x = (lane < 8) ? red[lane] : -INFINITY;
#pragma unroll
        for (int o = 4; o > 0; o >>= 1) x = fmaxf(x, __shfl_xor_sync(0xffffffffu, x, o));
        if (lane == 0) bcast = x;
    }
    __syncthreads();
    m = bcast;

    float sum = 0.f;
    for (int i = s + tid; i < e; i += 256) sum += expf(g_gate[i] - m);
#pragma unroll
    for (int o = 16; o > 0; o >>= 1) sum += __shfl_xor_sync(0xffffffffu, sum, o);
    if (lane == 0) red[wid] = sum;
    __syncthreads();
    if (wid == 0) {
        float x = (lane < 8) ? red[lane] : 0.f;
#pragma unroll
        for (int o = 4; o > 0; o >>= 1) x += __shfl_xor_sync(0xffffffffu, x, o);
        if (lane == 0) bcast = x;
    }
    __syncthreads();
    float inv = (e > s) ? 1.f / bcast : 0.f;

    float acc0 = 0.f, acc1 = 0.f;
    for (int start = s; start < e; start += 256) {
        int i = start + tid;
        salpha[tid] = (i < e) ? expf(g_gate[i] - m) * inv : 0.f;
        __syncthreads();
        int cnt = min(256, e - start);
        for (int k = 0; k < cnt; k++) {
            float a = salpha[k];
            const float* xr = g_buf0 + (size_t)(start + k) * 512;
            acc0 += xr[tid] * a;
            acc1 += xr[tid + 256] * a;
        }
        __syncthreads();
    }
    g_emb[g * 512 + tid] = acc0;
    g_emb[g * 512 + 256 + tid] = acc1;
}

// ---------------- GRU cell with h=0: out = (1-z)*n ; gh = bhh (whh unused) ----------------
__global__ void __launch_bounds__(256) gru_cell_kernel(
    const float* __restrict__ xin, const float* __restrict__ wih,
    const float* __restrict__ bih, const float* __restrict__ bhh,
    float* __restrict__ hout, int K)
{
    int warp = (blockIdx.x * blockDim.x + threadIdx.x) >> 5;
    int lane = threadIdx.x & 31;
    if (warp >= N_GRAPHS * GRUH) return;
    int g = warp >> 8;
    int j = warp & 255;
    const float* xg = xin + (size_t)g * K;
    const float* wr = wih + (size_t)j * K;
    const float* wz = wih + (size_t)(j + 256) * K;
    const float* wn = wih + (size_t)(j + 512) * K;
    float sr = 0.f, sz = 0.f, sn = 0.f;
    for (int k = lane; k < K; k += 32) {
        float xv = xg[k];
        sr += xv * wr[k];
        sz += xv * wz[k];
        sn += xv * wn[k];
    }
#pragma unroll
    for (int o = 16; o > 0; o >>= 1) {
        sr += __shfl_xor_sync(0xffffffffu, sr, o);
        sz += __shfl_xor_sync(0xffffffffu, sz, o);
        sn += __shfl_xor_sync(0xffffffffu, sn, o);
    }
    if (lane == 0) {
        float r = 1.f / (1.f + expf(-(sr + bih[j] + bhh[j])));
        float z = 1.f / (1.f + expf(-(sz + bih[j + 256] + bhh[j + 256])));
        float n = tanhf(sn + bih[j + 512] + r * bhh[j + 512]);
        hout[g * GRUH + j] = (1.f - z) * n;
    }
}

// ---------------- output projection ----------------
__global__ void __launch_bounds__(256) proj_kernel(
    const float* __restrict__ h2, const float* __restrict__ pw,
    const float* __restrict__ pb, float* __restrict__ out)
{
    int warp = (blockIdx.x * blockDim.x + threadIdx.x) >> 5;
    int lane = threadIdx.x & 31;
    if (warp >= N_GRAPHS * 512) return;
    int g = warp >> 9;
    int o = warp & 511;
    const float* hr = h2 + (size_t)g * 256;
    const float* wr = pw + (size_t)o * 256;
    float s = 0.f;
#pragma unroll 4
    for (int k = lane; k < 256; k += 32) s += hr[k] * wr[k];
#pragma unroll
    for (int d = 16; d > 0; d >>= 1) s += __shfl_xor_sync(0xffffffffu, s, d);
    if (lane == 0) out[g * 512 + o] = s + pb[o];
}

// ---------------- launch ----------------
extern "C" void kernel_launch(void* const* d_in, const int* in_sizes, int n_in,
                              void* d_out, int out_size)
{
    const float* x       = (const float*)d_in[0];
    const void*  ei      = d_in[1];
    const void*  batch   = d_in[2];
    const float* w0 = (const float*)d_in[3];  const float* b0 = (const float*)d_in[4];
    const float* w1 = (const float*)d_in[5];  const float* b1 = (const float*)d_in[6];
    const float* w2 = (const float*)d_in[7];  const float* b2 = (const float*)d_in[8];
    const float* gate_w = (const float*)d_in[9];
    const float* gate_b = (const float*)d_in[10];
    const float* wih0 = (const float*)d_in[11];
    const float* bih0 = (const float*)d_in[13];
    const float* bhh0 = (const float*)d_in[14];
    const float* wih1 = (const float*)d_in[15];
    const float* bih1 = (const float*)d_in[17];
    const float* bhh1 = (const float*)d_in[18];
    const float* proj_w = (const float*)d_in[19];
    const float* proj_b = (const float*)d_in[20];
    float* out = (float*)d_out;

    float *pH, *pB0, *pB1, *pEmb, *pH1, *pH2;
    cudaGetSymbolAddress((void**)&pH,   g_h);
    cudaGetSymbolAddress((void**)&pB0,  g_buf0);
    cudaGetSymbolAddress((void**)&pB1,  g_buf1);
    cudaGetSymbolAddress((void**)&pEmb, g_emb);
    cudaGetSymbolAddress((void**)&pH1,  g_h1);
    cudaGetSymbolAddress((void**)&pH2,  g_h2);

    // preprocessing: index width, degrees, CSR offsets (hierarchical scan), norms
    detect_kernel<<<1, 32>>>((const int*)ei);
    init_kernel<<<256, 256>>>();
    count_kernel<<<1024, 256>>>(ei, batch);
    part_sum_kernel<<<NPART, 256>>>();
    scan_parts_kernel<<<1, 256>>>();
    final_scan_kernel<<<NPART, 256>>>();
    dinv_kernel<<<(N_NODES + 255) / 256, 256>>>();
    fill_kernel<<<1024, 256>>>(ei);

    int gM = (N_NODES + 127) / 128;
    int gAgg = (N_NODES + 7) / 8;

    // layer 0: Agg(x)[64] -> GEMM 64->128 + b0 + relu
    agg64w_kernel<<<gAgg, 256>>>(x, pB1);
    gemm_tc_kernel<<<dim3(gM, 1), 256>>>(pB1, w0, b0, pH, N_NODES, 128, 64);
    // layer 1: Agg[128] -> GEMM 128->256 + b1 + relu
    agg128w_kernel<<<gAgg, 256>>>(pH, pB1);
    gemm_tc_kernel<<<dim3(gM, 2), 256>>>(pB1, w1, b1, pH, N_NODES, 256, 128);
    // layer 2: Agg[256] -> GEMM 256->512 + b2 + relu
    agg256w_kernel<<<gAgg, 256>>>(pH, pB1);
    gemm_tc_kernel<<<dim3(gM, 4), 256>>>(pB1, w2, b2, pB0, N_NODES, 512, 256);

    // attentional aggregation
    gate_kernel<<<(N_NODES * 32 + 255) / 256, 256>>>(gate_w, gate_b);
    softmax_emb_kernel<<<N_GRAPHS, 256>>>();

    // GRU (seq_len=1, h0=0 for both cells) + projection
    gru_cell_kernel<<<(N_GRAPHS * GRUH * 32) / 256, 256>>>(pEmb, wih0, bih0, bhh0, pH1, 512);
    gru_cell_kernel<<<(N_GRAPHS * GRUH * 32) / 256, 256>>>(pH1, wih1, bih1, bhh1, pH2, 256);
    proj_kernel<<<(N_GRAPHS * 512 * 32) / 256, 256>>>(pH2, proj_w, proj_b, out);
}

// round 7
// speedup vs baseline: 2.1116x; 1.3197x over previous
#include <cuda_runtime.h>
#include <cuda_bf16.h>
#include <math.h>
#include <stdint.h>

#define N_NODES  50000
#define N_EDGES  800000
#define N_GRAPHS 256
#define DMAX     512
#define GRUH     256
#define NPART    196   // ceil(50000/256)

// ---------------- scratch (device globals; no allocation allowed) ----------------
__device__ __align__(16) float g_h   [(size_t)N_NODES * DMAX];
__device__ __align__(16) float g_buf0[(size_t)N_NODES * DMAX];
__device__ __align__(16) float g_buf1[(size_t)N_NODES * DMAX];
__device__ float g_dinv[N_NODES];
__device__ int   g_counts[N_NODES];
__device__ int   g_cursor[N_NODES];
__device__ int   g_offs[N_NODES + 1];
__device__ int   g_part[NPART];
__device__ int   g_csrc[N_EDGES];
__device__ int   g_gcounts[N_GRAPHS];
__device__ int   g_goffs[N_GRAPHS + 1];
__device__ float g_gate[N_NODES];
__device__ __align__(16) float g_emb[N_GRAPHS * 512];
__device__ float g_h1[N_GRAPHS * GRUH];
__device__ float g_h2[N_GRAPHS * GRUH];
__device__ int   g_is64;

// ---------------- index-width detection (parallel: 1 warp, MLP=4/lane) ----------------
__global__ void detect_kernel(const int* __restrict__ ei_raw) {
    int lane = threadIdx.x;
    int bad = 0;
#pragma unroll
    for (int i = 0; i < 4; i++) bad |= ei_raw[2 * (lane + i * 32) + 1];
    unsigned m = __ballot_sync(0xffffffffu, bad != 0);
    if (lane == 0) g_is64 = (m == 0) ? 1 : 0;
}

__device__ __forceinline__ int load_idx(const void* p, long long i, int is64) {
    return is64 ? (int)((const long long*)p)[i] : ((const int*)p)[i];
}

// ---------------- init / degree count / CSR build ----------------
__global__ void init_kernel() {
    int i = blockIdx.x * blockDim.x + threadIdx.x;
    int stride = gridDim.x * blockDim.x;
    for (int k = i; k < N_NODES; k += stride) { g_counts[k] = 0; g_cursor[k] = 0; }
    for (int k = i; k < N_GRAPHS; k += stride) g_gcounts[k] = 0;
}

__global__ void count_kernel(const void* __restrict__ ei, const void* __restrict__ batch) {
    int is64 = g_is64;
    int i = blockIdx.x * blockDim.x + threadIdx.x;
    int stride = gridDim.x * blockDim.x;
    for (int e = i; e < N_EDGES; e += stride) {
        int d = load_idx(ei, (long long)N_EDGES + e, is64);   // dst = edge_index[1]
        atomicAdd(&g_counts[d], 1);
    }
    for (int v = i; v < N_NODES; v += stride) {
        int b = load_idx(batch, v, is64);
        atomicAdd(&g_gcounts[b], 1);
    }
}

// -------- hierarchical exclusive scan of g_counts -> g_offs (+ fused dinv) --------
__global__ void __launch_bounds__(256) part_sum_kernel() {
    __shared__ int red[8];
    int b = blockIdx.x, t = threadIdx.x;
    int i = b * 256 + t;
    int cnt = (i < N_NODES) ? g_counts[i] : 0;
    if (i < N_NODES) g_dinv[i] = rsqrtf((float)(cnt + 1));  // +1 self-loop
    int v = cnt;
#pragma unroll
    for (int o = 16; o > 0; o >>= 1) v += __shfl_xor_sync(0xffffffffu, v, o);
    if ((t & 31) == 0) red[t >> 5] = v;
    __syncthreads();
    if (t == 0) {
        int s = 0;
#pragma unroll
        for (int w = 0; w < 8; w++) s += red[w];
        g_part[b] = s;
    }
}

__global__ void __launch_bounds__(256) scan_parts_kernel() {
    __shared__ int sh[256];
    int t = threadIdx.x;
    int v = (t < NPART) ? g_part[t] : 0;
    sh[t] = v;
    __syncthreads();
    for (int d = 1; d < 256; d <<= 1) {
        int x = (t >= d) ? sh[t - d] : 0;
        __syncthreads();
        sh[t] += x;
        __syncthreads();
    }
    if (t < NPART) g_part[t] = sh[t] - v;
    __syncthreads();
    int gc = g_gcounts[t];
    sh[t] = gc;
    __syncthreads();
    for (int d = 1; d < 256; d <<= 1) {
        int x = (t >= d) ? sh[t - d] : 0;
        __syncthreads();
        sh[t] += x;
        __syncthreads();
    }
    g_goffs[t] = sh[t] - gc;
    if (t == 255) g_goffs[256] = sh[255];
}

__global__ void __launch_bounds__(256) final_scan_kernel() {
    __shared__ int sh[256];
    int b = blockIdx.x, t = threadIdx.x;
    int i = b * 256 + t;
    int v = (i < N_NODES) ? g_counts[i] : 0;
    sh[t] = v;
    __syncthreads();
    for (int d = 1; d < 256; d <<= 1) {
        int x = (t >= d) ? sh[t - d] : 0;
        __syncthreads();
        sh[t] += x;
        __syncthreads();
    }
    int base = g_part[b];
    if (i < N_NODES) g_offs[i] = base + sh[t] - v;
    if (i == N_NODES - 1) g_offs[N_NODES] = base + sh[t];
}

__global__ void fill_kernel(const void* __restrict__ ei) {
    int is64 = g_is64;
    int i = blockIdx.x * blockDim.x + threadIdx.x;
    int stride = gridDim.x * blockDim.x;
    for (int e = i; e < N_EDGES; e += stride) {
        int d = load_idx(ei, (long long)N_EDGES + e, is64);
        int s = load_idx(ei, e, is64);
        int pos = g_offs[d] + atomicAdd(&g_cursor[d], 1);
        g_csrc[pos] = s;
    }
}

// ------------- GCN aggregation BEFORE transform (Agg(X)·W == Agg(X·W)) -------------
// warp-per-node, unrolled x2 for MLP on the L2 latency path.
__global__ void __launch_bounds__(256) agg64w_kernel(const float* __restrict__ h,
                                                     float* __restrict__ out)
{
    int node = blockIdx.x * 8 + (threadIdx.x >> 5);
    if (node >= N_NODES) return;
    int lane = threadIdx.x & 31;
    float wd = g_dinv[node];
    float2 acc = *(const float2*)(h + (size_t)node * 64 + lane * 2);
    float ws = wd * wd;
    acc.x *= ws; acc.y *= ws;
    int e = g_offs[node], e1 = g_offs[node + 1];
    for (; e + 2 <= e1; e += 2) {
        int s0 = g_csrc[e], s1 = g_csrc[e + 1];
        float w0 = g_dinv[s0] * wd, w1 = g_dinv[s1] * wd;
        float2 v0 = *(const float2*)(h + (size_t)s0 * 64 + lane * 2);
        float2 v1 = *(const float2*)(h + (size_t)s1 * 64 + lane * 2);
        acc.x += v0.x * w0 + v1.x * w1;
        acc.y += v0.y * w0 + v1.y * w1;
    }
    if (e < e1) {
        int s0 = g_csrc[e];
        float w0 = g_dinv[s0] * wd;
        float2 v0 = *(const float2*)(h + (size_t)s0 * 64 + lane * 2);
        acc.x += v0.x * w0; acc.y += v0.y * w0;
    }
    *(float2*)(out + (size_t)node * 64 + lane * 2) = acc;
}

__global__ void __launch_bounds__(256) agg128w_kernel(const float* __restrict__ h,
                                                      float* __restrict__ out)
{
    int node = blockIdx.x * 8 + (threadIdx.x >> 5);
    if (node >= N_NODES) return;
    int lane = threadIdx.x & 31;
    float wd = g_dinv[node];
    float4 acc = *(const float4*)(h + (size_t)node * 128 + lane * 4);
    float ws = wd * wd;
    acc.x *= ws; acc.y *= ws; acc.z *= ws; acc.w *= ws;
    int e = g_offs[node], e1 = g_offs[node + 1];
    for (; e + 2 <= e1; e += 2) {
        int s0 = g_csrc[e], s1 = g_csrc[e + 1];
        float w0 = g_dinv[s0] * wd, w1 = g_dinv[s1] * wd;
        float4 v0 = *(const float4*)(h + (size_t)s0 * 128 + lane * 4);
        float4 v1 = *(const float4*)(h + (size_t)s1 * 128 + lane * 4);
        acc.x += v0.x * w0 + v1.x * w1;
        acc.y += v0.y * w0 + v1.y * w1;
        acc.z += v0.z * w0 + v1.z * w1;
        acc.w += v0.w * w0 + v1.w * w1;
    }
    if (e < e1) {
        int s0 = g_csrc[e];
        float w0 = g_dinv[s0] * wd;
        float4 v0 = *(const float4*)(h + (size_t)s0 * 128 + lane * 4);
        acc.x += v0.x * w0; acc.y += v0.y * w0;
        acc.z += v0.z * w0; acc.w += v0.w * w0;
    }
    *(float4*)(out + (size_t)node * 128 + lane * 4) = acc;
}

__global__ void __launch_bounds__(256) agg256w_kernel(const float* __restrict__ h,
                                                      float* __restrict__ out)
{
    int node = blockIdx.x * 8 + (threadIdx.x >> 5);
    if (node >= N_NODES) return;
    int lane = threadIdx.x & 31;
    float wd = g_dinv[node];
    const float* rown = h + (size_t)node * 256;
    float4 a0 = *(const float4*)(rown + lane * 4);
    float4 a1 = *(const float4*)(rown + 128 + lane * 4);
    float ws = wd * wd;
    a0.x *= ws; a0.y *= ws; a0.z *= ws; a0.w *= ws;
    a1.x *= ws; a1.y *= ws; a1.z *= ws; a1.w *= ws;
    int e = g_offs[node], e1 = g_offs[node + 1];
    for (; e + 2 <= e1; e += 2) {
        int s0 = g_csrc[e], s1 = g_csrc[e + 1];
        float w0 = g_dinv[s0] * wd, w1 = g_dinv[s1] * wd;
        const float* r0 = h + (size_t)s0 * 256;
        const float* r1 = h + (size_t)s1 * 256;
        float4 u0 = *(const float4*)(r0 + lane * 4);
        float4 u1 = *(const float4*)(r0 + 128 + lane * 4);
        float4 v0 = *(const float4*)(r1 + lane * 4);
        float4 v1 = *(const float4*)(r1 + 128 + lane * 4);
        a0.x += u0.x * w0 + v0.x * w1; a0.y += u0.y * w0 + v0.y * w1;
        a0.z += u0.z * w0 + v0.z * w1; a0.w += u0.w * w0 + v0.w * w1;
        a1.x += u1.x * w0 + v1.x * w1; a1.y += u1.y * w0 + v1.y * w1;
        a1.z += u1.z * w0 + v1.z * w1; a1.w += u1.w * w0 + v1.w * w1;
    }
    if (e < e1) {
        int s0 = g_csrc[e];
        float w0 = g_dinv[s0] * wd;
        const float* r0 = h + (size_t)s0 * 256;
        float4 u0 = *(const float4*)(r0 + lane * 4);
        float4 u1 = *(const float4*)(r0 + 128 + lane * 4);
        a0.x += u0.x * w0; a0.y += u0.y * w0; a0.z += u0.z * w0; a0.w += u0.w * w0;
        a1.x += u1.x * w0; a1.y += u1.y * w0; a1.z += u1.z * w0; a1.w += u1.w * w0;
    }
    float* ro = out + (size_t)node * 256;
    *(float4*)(ro + lane * 4) = a0;
    *(float4*)(ro + 128 + lane * 4) = a1;
}

// ---------------- bf16 3-term split helpers (fp32-near accuracy) ----------------
__device__ __forceinline__ void split_bf16(float x, __nv_bfloat16& h, __nv_bfloat16& l) {
    h = __float2bfloat16(x);
    l = __float2bfloat16(x - __bfloat162float(h));
}
__device__ __forceinline__ uint32_t pk_bf(__nv_bfloat16 a, __nv_bfloat16 b) {
    __nv_bfloat162 v(a, b);
    return *(uint32_t*)&v;
}
__device__ __forceinline__ void mma_bf16(float* c, const uint32_t* a, const uint32_t* b) {
    asm volatile(
        "mma.sync.aligned.m16n8k16.row.col.f32.bf16.bf16.f32 "
        "{%0,%1,%2,%3}, {%4,%5,%6,%7}, {%8,%9}, {%0,%1,%2,%3};"
        : "+f"(c[0]), "+f"(c[1]), "+f"(c[2]), "+f"(c[3])
        : "r"(a[0]), "r"(a[1]), "r"(a[2]), "r"(a[3]), "r"(b[0]), "r"(b[1]));
}

// ---- GEMM + bias + ReLU via bf16 tensor cores (3-term split):
//      C = relu(A[M,K] @ B[K,N] + bias)
// CTA tile 128x128, BK=32; 8 warps 2(M)x4(N); warp = 64x32 = 4x4 m16n8k16 tiles.
#define ASTR2 40    // bf16 stride for A hi/lo tiles (conflict-free fragment loads)
#define BSTR 132    // fp32 stride for B tile

__global__ void __launch_bounds__(256) gemm_tc_kernel(
    const float* __restrict__ A, const float* __restrict__ B,
    const float* __restrict__ bias, float* __restrict__ C,
    int M, int N, int K)
{
    __shared__ __align__(16) __nv_bfloat16 Ah[128 * ASTR2];
    __shared__ __align__(16) __nv_bfloat16 Al[128 * ASTR2];
    __shared__ __align__(16) float Bs[32 * BSTR];

    int tid = threadIdx.x;
    int lane = tid & 31;
    int wid = tid >> 5;
    int warp_m = wid >> 2;         // 0..1
    int warp_n = wid & 3;          // 0..3
    int g = lane >> 2;             // group 0..7
    int t = lane & 3;              // thread-in-group 0..3
    int row0 = blockIdx.x * 128;
    int col0 = blockIdx.y * 128;

    float acc[4][4][4];
#pragma unroll
    for (int i = 0; i < 4; i++)
#pragma unroll
        for (int j = 0; j < 4; j++)
#pragma unroll
            for (int r = 0; r < 4; r++) acc[i][j][r] = 0.f;

    for (int k0 = 0; k0 < K; k0 += 32) {
        // load + split A tile [128 x 32] into bf16 hi/lo (guarded on M)
#pragma unroll
        for (int l = 0; l < 4; l++) {
            int f = tid + l * 256;
            int r = f >> 3;
            int c4 = f & 7;
            int grow = row0 + r;
            float4 v = make_float4(0.f, 0.f, 0.f, 0.f);
            if (grow < M) v = *(const float4*)(A + (size_t)grow * K + k0 + c4 * 4);
            __nv_bfloat16 h0, l0, h1, l1, h2, l2, h3, l3;
            split_bf16(v.x, h0, l0); split_bf16(v.y, h1, l1);
            split_bf16(v.z, h2, l2); split_bf16(v.w, h3, l3);
            int base = r * ASTR2 + c4 * 4;
            *(uint32_t*)&Ah[base]     = pk_bf(h0, h1);
            *(uint32_t*)&Ah[base + 2] = pk_bf(h2, h3);
            *(uint32_t*)&Al[base]     = pk_bf(l0, l1);
            *(uint32_t*)&Al[base + 2] = pk_bf(l2, l3);
        }
        // load B tile [32 x 128] fp32
#pragma unroll
        for (int l = 0; l < 4; l++) {
            int f = tid + l * 256;
            int kk = f >> 5;
            int c4 = f & 31;
            float4 v = *(const float4*)(B + (size_t)(k0 + kk) * N + col0 + c4 * 4);
            *(float4*)&Bs[kk * BSTR + c4 * 4] = v;
        }
        __syncthreads();

#pragma unroll
        for (int kc = 0; kc < 2; kc++) {       // two k16 chunks per BK=32
            // B fragments (split on the fly) for 4 n-tiles
            uint32_t bh[4][2], bl[4][2];
#pragma unroll
            for (int tn = 0; tn < 4; tn++) {
                int n = warp_n * 32 + tn * 8 + g;
                const float* bp = &Bs[(kc * 16 + 2 * t) * BSTR + n];
                float b0 = bp[0];
                float b1 = bp[BSTR];
                float b2 = bp[8 * BSTR];
                float b3 = bp[9 * BSTR];
                __nv_bfloat16 h0, l0, h1, l1, h2, l2, h3, l3;
                split_bf16(b0, h0, l0); split_bf16(b1, h1, l1);
                split_bf16(b2, h2, l2); split_bf16(b3, h3, l3);
                bh[tn][0] = pk_bf(h0, h1); bh[tn][1] = pk_bf(h2, h3);
                bl[tn][0] = pk_bf(l0, l1); bl[tn][1] = pk_bf(l2, l3);
            }
#pragma unroll
            for (int tm = 0; tm < 4; tm++) {
                int row = warp_m * 64 + tm * 16 + g;
                int base = row * ASTR2 + kc * 16 + 2 * t;
                uint32_t ah[4], al[4];
                ah[0] = *(const uint32_t*)&Ah[base];
                ah[1] = *(const uint32_t*)&Ah[base + 8 * ASTR2];
                ah[2] = *(const uint32_t*)&Ah[base + 8];
                ah[3] = *(const uint32_t*)&Ah[base + 8 * ASTR2 + 8];
                al[0] = *(const uint32_t*)&Al[base];
                al[1] = *(const uint32_t*)&Al[base + 8 * ASTR2];
                al[2] = *(const uint32_t*)&Al[base + 8];
                al[3] = *(const uint32_t*)&Al[base + 8 * ASTR2 + 8];
#pragma unroll
                for (int tn = 0; tn < 4; tn++) {
                    mma_bf16(acc[tm][tn], al, bh[tn]);
                    mma_bf16(acc[tm][tn], ah, bl[tn]);
                    mma_bf16(acc[tm][tn], ah, bh[tn]);
                }
            }
        }
        __syncthreads();
    }

    // epilogue: bias + relu, guarded store
#pragma unroll
    for (int tn = 0; tn < 4; tn++) {
        int col = col0 + warp_n * 32 + tn * 8 + 2 * t;
        float bv0 = bias[col];
        float bv1 = bias[col + 1];
#pragma unroll
        for (int tm = 0; tm < 4; tm++) {
            int row = row0 + warp_m * 64 + tm * 16 + g;
            if (row < M) {
                float2 v;
                v.x = fmaxf(acc[tm][tn][0] + bv0, 0.f);
                v.y = fmaxf(acc[tm][tn][1] + bv1, 0.f);
                *(float2*)(C + (size_t)row * N + col) = v;
            }
            if (row + 8 < M) {
                float2 v;
                v.x = fmaxf(acc[tm][tn][2] + bv0, 0.f);
                v.y = fmaxf(acc[tm][tn][3] + bv1, 0.f);
                *(float2*)(C + (size_t)(row + 8) * N + col) = v;
            }
        }
    }
}

// ---------------- gate scores: gate[i] = dot(x[i,0:512], gate_w) + gate_b ----------------
__global__ void __launch_bounds__(256) gate_kernel(const float* __restrict__ gw,
                                                   const float* __restrict__ gb)
{
    int warp = (blockIdx.x * blockDim.x + threadIdx.x) >> 5;
    int lane = threadIdx.x & 31;
    if (warp >= N_NODES) return;
    const float* xr = g_buf0 + (size_t)warp * 512;
    float s = 0.f;
#pragma unroll 4
    for (int k = lane; k < 512; k += 32) s += xr[k] * gw[k];
#pragma unroll
    for (int o = 16; o > 0; o >>= 1) s += __shfl_xor_sync(0xffffffffu, s, o);
    if (lane == 0) g_gate[warp] = s + gb[0];
}

// ---------------- segment softmax + weighted sum -> graph embeddings [G, 512] ----------------
__global__ void __launch_bounds__(256) softmax_emb_kernel()
{
    __shared__ float red[8];
    __shared__ float salpha[256];
    __shared__ float bcast;
    int g = blockIdx.x, tid = threadIdx.x;
    int lane = tid & 31, wid = tid >> 5;
    int s = g_goffs[g], e = g_goffs[g + 1];

    float m = -INFINITY;
    for (int i = s + tid; i < e; i += 256) m = fmaxf(m, g_gate[i]);
#pragma unroll
    for (int o = 16; o > 0; o >>= 1) m = fmaxf(m, __shfl_xor_sync(0xffffffffu, m, o));
    if (lane == 0) red[wid] = m;
    __syncthreads();
    if (wid == 0) {
        float x = (lane < 8) ? red[lane] : -INFINITY;
#pragma unroll
        for (int o = 4; o > 0; o >>= 1) x = fmaxf(x, __shfl_xor_sync(0xffffffffu, x, o));
        if (lane == 0) bcast = x;
    }
    __syncthreads();
    m = bcast;

    float sum = 0.f;
    for (int i = s + tid; i < e; i += 256) sum += expf(g_gate[i] - m);
#pragma unroll
    for (int o = 16; o > 0; o >>= 1) sum += __shfl_xor_sync(0xffffffffu, sum, o);
    if (lane == 0) red[wid] = sum;
    __syncthreads();
    if (wid == 0) {
        float x = (lane < 8) ? red[lane] : 0.f;
#pragma unroll
        for (int o = 4; o > 0; o >>= 1) x += __shfl_xor_sync(0xffffffffu, x, o);
        if (lane == 0) bcast = x;
    }
    __syncthreads();
    float inv = (e > s) ? 1.f / bcast : 0.f;

    float acc0 = 0.f, acc1 = 0.f;
    for (int start = s; start < e; start += 256) {
        int i = start + tid;
        salpha[tid] = (i < e) ? expf(g_gate[i] - m) * inv : 0.f;
        __syncthreads();
        int cnt = min(256, e - start);
        for (int k = 0; k < cnt; k++) {
            float a = salpha[k];
            const float* xr = g_buf0 + (size_t)(start + k) * 512;
            acc0 += xr[tid] * a;
            acc1 += xr[tid + 256] * a;
        }
        __syncthreads();
    }
    g_emb[g * 512 + tid] = acc0;
    g_emb[g * 512 + 256 + tid] = acc1;
}

// ---------------- GRU cell with h=0: out = (1-z)*n ; gh = bhh (whh unused) ----------------
__global__ void __launch_bounds__(256) gru_cell_kernel(
    const float* __restrict__ xin, const float* __restrict__ wih,
    const float* __restrict__ bih, const float* __restrict__ bhh,
    float* __restrict__ hout, int K)
{
    int warp = (blockIdx.x * blockDim.x + threadIdx.x) >> 5;
    int lane = threadIdx.x & 31;
    if (warp >= N_GRAPHS * GRUH) return;
    int g = warp >> 8;
    int j = warp & 255;
    const float* xg = xin + (size_t)g * K;
    const float* wr = wih + (size_t)j * K;
    const float* wz = wih + (size_t)(j + 256) * K;
    const float* wn = wih + (size_t)(j + 512) * K;
    float sr = 0.f, sz = 0.f, sn = 0.f;
    for (int k = lane; k < K; k += 32) {
        float xv = xg[k];
        sr += xv * wr[k];
        sz += xv * wz[k];
        sn += xv * wn[k];
    }
#pragma unroll
    for (int o = 16; o > 0; o >>= 1) {
        sr += __shfl_xor_sync(0xffffffffu, sr, o);
        sz += __shfl_xor_sync(0xffffffffu, sz, o);
        sn += __shfl_xor_sync(0xffffffffu, sn, o);
    }
    if (lane == 0) {
        float r = 1.f / (1.f + expf(-(sr + bih[j] + bhh[j])));
        float z = 1.f / (1.f + expf(-(sz + bih[j + 256] + bhh[j + 256])));
        float n = tanhf(sn + bih[j + 512] + r * bhh[j + 512]);
        hout[g * GRUH + j] = (1.f - z) * n;
    }
}

// ---------------- output projection ----------------
__global__ void __launch_bounds__(256) proj_kernel(
    const float* __restrict__ h2, const float* __restrict__ pw,
    const float* __restrict__ pb, float* __restrict__ out)
{
    int warp = (blockIdx.x * blockDim.x + threadIdx.x) >> 5;
    int lane = threadIdx.x & 31;
    if (warp >= N_GRAPHS * 512) return;
    int g = warp >> 9;
    int o = warp & 511;
    const float* hr = h2 + (size_t)g * 256;
    const float* wr = pw + (size_t)o * 256;
    float s = 0.f;
#pragma unroll 4
    for (int k = lane; k < 256; k += 32) s += hr[k] * wr[k];
#pragma unroll
    for (int d = 16; d > 0; d >>= 1) s += __shfl_xor_sync(0xffffffffu, s, d);
    if (lane == 0) out[g * 512 + o] = s + pb[o];
}

// ---------------- launch ----------------
extern "C" void kernel_launch(void* const* d_in, const int* in_sizes, int n_in,
                              void* d_out, int out_size)
{
    const float* x       = (const float*)d_in[0];
    const void*  ei      = d_in[1];
    const void*  batch   = d_in[2];
    const float* w0 = (const float*)d_in[3];  const float* b0 = (const float*)d_in[4];
    const float* w1 = (const float*)d_in[5];  const float* b1 = (const float*)d_in[6];
    const float* w2 = (const float*)d_in[7];  const float* b2 = (const float*)d_in[8];
    const float* gate_w = (const float*)d_in[9];
    const float* gate_b = (const float*)d_in[10];
    const float* wih0 = (const float*)d_in[11];
    const float* bih0 = (const float*)d_in[13];
    const float* bhh0 = (const float*)d_in[14];
    const float* wih1 = (const float*)d_in[15];
    const float* bih1 = (const float*)d_in[17];
    const float* bhh1 = (const float*)d_in[18];
    const float* proj_w = (const float*)d_in[19];
    const float* proj_b = (const float*)d_in[20];
    float* out = (float*)d_out;

    float *pH, *pB0, *pB1, *pEmb, *pH1, *pH2;
    cudaGetSymbolAddress((void**)&pH,   g_h);
    cudaGetSymbolAddress((void**)&pB0,  g_buf0);
    cudaGetSymbolAddress((void**)&pB1,  g_buf1);
    cudaGetSymbolAddress((void**)&pEmb, g_emb);
    cudaGetSymbolAddress((void**)&pH1,  g_h1);
    cudaGetSymbolAddress((void**)&pH2,  g_h2);

    // preprocessing: index width, degrees+dinv, CSR offsets (hierarchical scan)
    detect_kernel<<<1, 32>>>((const int*)ei);
    init_kernel<<<256, 256>>>();
    count_kernel<<<1024, 256>>>(ei, batch);
    part_sum_kernel<<<NPART, 256>>>();
    scan_parts_kernel<<<1, 256>>>();
    final_scan_kernel<<<NPART, 256>>>();
    fill_kernel<<<1024, 256>>>(ei);

    int gM = (N_NODES + 127) / 128;
    int gAgg = (N_NODES + 7) / 8;

    // layer 0: Agg(x)[64] -> GEMM 64->128 + b0 + relu
    agg64w_kernel<<<gAgg, 256>>>(x, pB1);
    gemm_tc_kernel<<<dim3(gM, 1), 256>>>(pB1, w0, b0, pH, N_NODES, 128, 64);
    // layer 1: Agg[128] -> GEMM 128->256 + b1 + relu
    agg128w_kernel<<<gAgg, 256>>>(pH, pB1);
    gemm_tc_kernel<<<dim3(gM, 2), 256>>>(pB1, w1, b1, pH, N_NODES, 256, 128);
    // layer 2: Agg[256] -> GEMM 256->512 + b2 + relu
    agg256w_kernel<<<gAgg, 256>>>(pH, pB1);
    gemm_tc_kernel<<<dim3(gM, 4), 256>>>(pB1, w2, b2, pB0, N_NODES, 512, 256);

    // attentional aggregation
    gate_kernel<<<(N_NODES * 32 + 255) / 256, 256>>>(gate_w, gate_b);
    softmax_emb_kernel<<<N_GRAPHS, 256>>>();

    // GRU (seq_len=1, h0=0 for both cells) + projection
    gru_cell_kernel<<<(N_GRAPHS * GRUH * 32) / 256, 256>>>(pEmb, wih0, bih0, bhh0, pH1, 512);
    gru_cell_kernel<<<(N_GRAPHS * GRUH * 32) / 256, 256>>>(pH1, wih1, bih1, bhh1, pH2, 256);
    proj_kernel<<<(N_GRAPHS * 512 * 32) / 256, 256>>>(pH2, proj_w, proj_b, out);
}